// round 8
// baseline (speedup 1.0000x reference)
#include <cuda_runtime.h>
#include <cstdint>

// SigCubicalEcc round 8 = round 7 + 32-register cap (8 blocks/SM -> full occupancy).
// Per-pixel sigmoid max-decomposition (2 RCP + 1 SHFL per warp-row-step).
// One block per (image, step-group): 8 warps x 8 rows, smem reduction, single launch.
//
// ECC_j = Sum_v max(m, m_up) - Sum_eh max(s, s_up) - Sum_ev m + Sum_f s
// s = sigma(lam*(t_j - x)) per pixel, m = horizontal pair max; zero padding.
// sigma(lam(t-x)) = rcp(1 + ex2(K*x) * 2^{-K*t}),  K = LAM*log2(e).
// Overflow exact: ex2->inf, fma->inf, rcp.approx(inf)=0.

#define HH 64
#define WW 64
#define STEPS 32
#define GROUPS 16
#define SPG (STEPS / GROUPS)    // 2 steps per block
#define THREADS 256
#define NWARP 8
#define ROWS_PER_WARP 8
#define NIMG 192

__device__ __forceinline__ float ex2_approx(float x) {
    float y;
    asm("ex2.approx.ftz.f32 %0, %1;" : "=f"(y) : "f"(x));
    return y;
}
__device__ __forceinline__ float rcp_approx(float x) {
    float y;
    asm("rcp.approx.ftz.f32 %0, %1;" : "=f"(y) : "f"(x));
    return y;
}

__global__ __launch_bounds__(THREADS, 8)
void sig_cubical_ecc_kernel(const float* __restrict__ x, float* __restrict__ out) {
    __shared__ float red[NWARP][SPG];

    const int img   = blockIdx.x >> 4;           // / GROUPS
    const int group = blockIdx.x & (GROUPS - 1);
    const int tid   = threadIdx.x;
    const int lane  = tid & 31;
    const int warp  = tid >> 5;

    const float K = 200.0f * 1.4426950408889634f;   // LAM * log2(e)

    // c_j = 2^(-K * t_j) for this block's steps
    float cj[SPG];
#pragma unroll
    for (int jj = 0; jj < SPG; jj++) {
        int j = group * SPG + jj;
        float tj = 0.02f + (float)j * (0.26f / 31.0f);
        cj[jj] = ex2_approx(-K * tj);
    }

    const float* xi = x + (size_t)img * (HH * WW) + 2 * lane;
    const int r0 = warp * ROWS_PER_WARP;

    float sp0[SPG], sp1[SPG], mp0[SPG], mp1[SPG], acc[SPG];
#pragma unroll
    for (int jj = 0; jj < SPG; jj++) {
        sp0[jj] = 0.0f; sp1[jj] = 0.0f;
        mp0[jj] = 0.0f; mp1[jj] = 0.0f;
        acc[jj] = 0.0f;
    }

    // ---- halo row r0-1 (warp 0: row -1 is padding => all zeros) ----
    if (warp > 0) {
        float2 xv = *reinterpret_cast<const float2*>(xi + (r0 - 1) * WW);
        float ex = ex2_approx(xv.x * K);
        float ey = ex2_approx(xv.y * K);
#pragma unroll
        for (int jj = 0; jj < SPG; jj++) {
            float s0 = rcp_approx(fmaf(ex, cj[jj], 1.0f));
            float s1 = rcp_approx(fmaf(ey, cj[jj], 1.0f));
            float sn = __shfl_down_sync(0xffffffffu, s0, 1);
            sn = (lane == 31) ? 0.0f : sn;
            sp0[jj] = s0; sp1[jj] = s1;
            mp0[jj] = fmaxf(s0, s1);
            mp1[jj] = fmaxf(s1, sn);
        }
    }

    // ---- 8 data rows ----
#pragma unroll
    for (int i = 0; i < ROWS_PER_WARP; i++) {
        float2 xv = *reinterpret_cast<const float2*>(xi + (r0 + i) * WW);
        float ex = ex2_approx(xv.x * K);
        float ey = ex2_approx(xv.y * K);
#pragma unroll
        for (int jj = 0; jj < SPG; jj++) {
            float s0 = rcp_approx(fmaf(ex, cj[jj], 1.0f));
            float s1 = rcp_approx(fmaf(ey, cj[jj], 1.0f));
            float sn = __shfl_down_sync(0xffffffffu, s0, 1);
            sn = (lane == 31) ? 0.0f : sn;
            float m0 = fmaxf(s0, s1);
            float m1 = fmaxf(s1, sn);

            float eh    = fmaxf(s0, sp0[jj]);
            float ehsel = (lane == 0) ? s0 : eh;   // left-boundary cancellation
            acc[jj] += (fminf(s0, s1) - m1)
                     + (fmaxf(m0, mp0[jj]) - ehsel)
                     + (fmaxf(m1, mp1[jj]) - fmaxf(s1, sp1[jj]));

            sp0[jj] = s0; sp1[jj] = s1; mp0[jj] = m0; mp1[jj] = m1;
        }
    }

    // ---- bottom boundary (vertex row 64): the row below is all zeros ----
    if (warp == NWARP - 1) {
#pragma unroll
        for (int jj = 0; jj < SPG; jj++) {
            float ehsel = (lane == 0) ? 0.0f : sp0[jj];
            acc[jj] += (mp0[jj] - ehsel) + (mp1[jj] - sp1[jj]);
        }
    }

    // ---- warp reduce, then block reduce in smem, single store ----
#pragma unroll
    for (int jj = 0; jj < SPG; jj++) {
        float v = acc[jj];
#pragma unroll
        for (int o = 16; o > 0; o >>= 1)
            v += __shfl_xor_sync(0xffffffffu, v, o);
        if (lane == 0) red[warp][jj] = v;
    }
    __syncthreads();

    if (tid < SPG) {
        float s = 0.0f;
#pragma unroll
        for (int w = 0; w < NWARP; w++) s += red[w][tid];
        out[img * STEPS + group * SPG + tid] = s;
    }
}

extern "C" void kernel_launch(void* const* d_in, const int* in_sizes, int n_in,
                              void* d_out, int out_size) {
    const float* x = (const float*)d_in[0];
    float* out = (float*)d_out;

    sig_cubical_ecc_kernel<<<NIMG * GROUPS, THREADS>>>(x, out);
}